// round 15
// baseline (speedup 1.0000x reference)
#include <cuda_runtime.h>
#include <cuda_fp16.h>

#define DTC (1.0f/64.0f)
#define NSTEPS 64
#define NK 32
#define NRAYS 16384

// Delta fp16 template: entry (k,z,y,x) = 8 halves (16B):
// {c0,c1}@x, {c2,c3}@x, {dc0,dc1}, {dc2,dc3}  where dc = v@(x+1) - v@x
__device__ uint4 g_templ[NK * 16 * 16 * 16];

__global__ void repack_kernel(const float* __restrict__ t) {
    int idx = blockIdx.x * blockDim.x + threadIdx.x;  // over NK*4096 voxels
    if (idx >= NK * 4096) return;
    int k = idx >> 12;
    int v = idx & 4095;          // z*256 + y*16 + x
    int x = v & 15;
    int x1 = (x < 15) ? 1 : 0;
    const float* src = t + (size_t)k * 4 * 4096 + v;
    __half h[8];
    #pragma unroll
    for (int c = 0; c < 4; c++) {
        float v0 = src[c * 4096];
        float v1 = src[c * 4096 + x1];
        h[c]     = __float2half_rn(v0);
        h[4 + c] = __float2half_rn(v1 - v0);
    }
    g_templ[idx] = *reinterpret_cast<uint4*>(h);
}

__device__ __forceinline__ float warp_sum(float v) {
    #pragma unroll
    for (int off = 16; off; off >>= 1)
        v += __shfl_xor_sync(0xffffffffu, v, off);
    return v;
}

#define H2(u) (*reinterpret_cast<const __half2*>(&(u)))

// Block = 128 threads = 4 warps = 2 rays x 2 half-rays.
// Warp (ray, half): lane l handles step = half*32 + l.  Loop over primitives.
__global__ void __launch_bounds__(128) raymarch_kernel(
    const float* __restrict__ raypos, const float* __restrict__ raydir,
    const float* __restrict__ tminmax, const float* __restrict__ primpos,
    const float* __restrict__ primrot, const float* __restrict__ primscale,
    float* __restrict__ out)
{
    const int lane   = threadIdx.x & 31;
    const int warpid = threadIdx.x >> 5;
    const int ri     = warpid >> 1;       // ray index in block (0,1)
    const int half   = warpid & 1;        // which 32-step half
    const int ray    = blockIdx.x * 2 + ri;
    const unsigned FULL = 0xffffffffu;

    __shared__ float4 s_a[2][NK];   // {Bz, By, Bx, Dz}
    __shared__ float2 s_b[2][NK];   // {Dy, Dx}
    __shared__ float  s_base[2];
    __shared__ float  s_out[2][2][4];

    const float rpx = raypos[ray*3+0], rpy = raypos[ray*3+1], rpz = raypos[ray*3+2];
    const float rdx = raydir[ray*3+0], rdy = raydir[ray*3+1], rdz = raydir[ray*3+2];
    const float tmin = tminmax[ray*2+0], tmax = tminmax[ray*2+1];

    // ---- setup: lane = primitive ----
    const int kp = lane;
    const float px = primpos[kp*3+0], py = primpos[kp*3+1], pz = primpos[kp*3+2];
    const float r00 = primrot[kp*9+0], r01 = primrot[kp*9+1], r02 = primrot[kp*9+2];
    const float r10 = primrot[kp*9+3], r11 = primrot[kp*9+4], r12 = primrot[kp*9+5];
    const float r20 = primrot[kp*9+6], r21 = primrot[kp*9+7], r22 = primrot[kp*9+8];
    const float s0 = primscale[kp*3+0], s1 = primscale[kp*3+1], s2 = primscale[kp*3+2];

    const float wx = rpx - px, wy = rpy - py, wz = rpz - pz;
    const float Bz = fmaf(s0 * fmaf(r00, wx, fmaf(r01, wy, r02 * wz)), 7.5f, 7.5f);
    const float By = fmaf(s1 * fmaf(r10, wx, fmaf(r11, wy, r12 * wz)), 7.5f, 7.5f);
    const float Bx = fmaf(s2 * fmaf(r20, wx, fmaf(r21, wy, r22 * wz)), 7.5f, 7.5f);
    const float Dz = 7.5f * (s0 * fmaf(r00, rdx, fmaf(r01, rdy, r02 * rdz)));
    const float Dy = 7.5f * (s1 * fmaf(r10, rdx, fmaf(r11, rdy, r12 * rdz)));
    const float Dx = 7.5f * (s2 * fmaf(r20, rdx, fmaf(r21, rdy, r22 * rdz)));

    if (half == 0) {
        s_a[ri][lane] = make_float4(Bz, By, Bx, Dz);
        s_b[ri][lane] = make_float2(Dy, Dx);
    }

    // Per-prim slab interval in t (conservative)
    float ta = -1e30f, tb = 1e30f;
    {
        const float BB[3] = {Bz, By, Bx};
        const float DD[3] = {Dz, Dy, Dx};
        #pragma unroll
        for (int a = 0; a < 3; a++) {
            float B = BB[a], D = DD[a];
            if (fabsf(D) < 1e-9f) {
                if (B < 0.f || B > 15.f) { ta = 1e30f; tb = -1e30f; }
            } else {
                float inv = 1.0f / D;
                float u0 = (0.f  - B) * inv;
                float u1 = (15.f - B) * inv;
                ta = fmaxf(ta, fminf(u0, u1));
                tb = fminf(tb, fmaxf(u0, u1));
            }
        }
    }
    // This warp's t-range (widened by one step for fp safety)
    const float tlo = fmaf((float)(half * 32), DTC, tmin) - DTC;
    const float thi = fminf(fmaf((float)(half * 32 + 31), DTC, tmin), tmax) + DTC;
    bool overlap = (ta <= thi) && (tb >= tlo);
    unsigned mask = __ballot_sync(FULL, overlap);

    __syncthreads();

    // ---- march: lane = step ----
    const int  step  = half * 32 + lane;
    const float t    = fmaf((float)step, DTC, tmin);
    const bool valid = (t < tmax);

    float sr = 0.f, sg = 0.f, sb = 0.f, sa = 0.f;

    for (unsigned m = mask; m; m &= (m - 1)) {
        int k = __ffs(m) - 1;
        float4 A = s_a[ri][k];
        float2 Bv = s_b[ri][k];
        float gz = fmaf(t, A.w,  A.x);
        float gy = fmaf(t, Bv.x, A.y);
        float gx = fmaf(t, Bv.y, A.z);
        bool inside = valid &&
                      fminf(fminf(gz, gy), gx) >= 0.f &&
                      fmaxf(fmaxf(gz, gy), gx) <= 15.f;
        if (!__ballot_sync(FULL, inside)) continue;

        float izf = fminf(fmaxf(floorf(gz), 0.f), 14.f);
        float iyf = fminf(fmaxf(floorf(gy), 0.f), 14.f);
        float ixf = fminf(fmaxf(floorf(gx), 0.f), 14.f);
        float fz = gz - izf;
        __half2 fx2 = __float2half2_rn(gx - ixf);
        __half2 fy2 = __float2half2_rn(gy - iyf);

        const uint4* p = g_templ + (k << 12) +
                         (((int)izf) << 8) + (((int)iyf) << 4) + (int)ixf;
        const uint4 Z4 = make_uint4(0u, 0u, 0u, 0u);
        uint4 e00 = inside ? __ldg(p)       : Z4;
        uint4 e01 = inside ? __ldg(p + 16)  : Z4;
        uint4 e10 = inside ? __ldg(p + 256) : Z4;
        uint4 e11 = inside ? __ldg(p + 272) : Z4;

        // x-lerp via delta form: v = base + fx*delta
        __half2 a00 = __hfma2(fx2, H2(e00.z), H2(e00.x));
        __half2 b00 = __hfma2(fx2, H2(e00.w), H2(e00.y));
        __half2 a01 = __hfma2(fx2, H2(e01.z), H2(e01.x));
        __half2 b01 = __hfma2(fx2, H2(e01.w), H2(e01.y));
        __half2 a10 = __hfma2(fx2, H2(e10.z), H2(e10.x));
        __half2 b10 = __hfma2(fx2, H2(e10.w), H2(e10.y));
        __half2 a11 = __hfma2(fx2, H2(e11.z), H2(e11.x));
        __half2 b11 = __hfma2(fx2, H2(e11.w), H2(e11.y));
        // y-lerp
        __half2 z0a = __hfma2(fy2, __hsub2(a01, a00), a00);
        __half2 z0b = __hfma2(fy2, __hsub2(b01, b00), b00);
        __half2 z1a = __hfma2(fy2, __hsub2(a11, a10), a10);
        __half2 z1b = __hfma2(fy2, __hsub2(b11, b10), b10);
        // z-lerp fp32
        float2 f0a = __half22float2(z0a), f0b = __half22float2(z0b);
        float2 f1a = __half22float2(z1a), f1b = __half22float2(z1b);
        sr += fmaf(fz, f1a.x - f0a.x, f0a.x);
        sg += fmaf(fz, f1a.y - f0a.y, f0a.y);
        sb += fmaf(fz, f1b.x - f0b.x, f0b.x);
        sa += fmaf(fz, f1b.y - f0b.y, f0b.y);
    }

    // ---- compositing: prefix scan over steps (sa >= 0 so alpha = min(cum,1)) ----
    float saDT = sa * DTC;
    float cum = saDT;
    #pragma unroll
    for (int off = 1; off < 32; off <<= 1) {
        float n = __shfl_up_sync(FULL, cum, off);
        if (lane >= off) cum += n;
    }
    if (half == 0 && lane == 31) s_base[ri] = cum;
    __syncthreads();
    float base = (half == 1) ? s_base[ri] : 0.f;
    float cumi = base + cum;
    float exi  = cumi - saDT;
    float contrib = fminf(cumi, 1.0f) - fminf(exi, 1.0f);

    float pr = warp_sum(sr * contrib);
    float pg = warp_sum(sg * contrib);
    float pb = warp_sum(sb * contrib);

    if (lane == 31) {
        s_out[ri][half][0] = pr;
        s_out[ri][half][1] = pg;
        s_out[ri][half][2] = pb;
        s_out[ri][half][3] = cumi;      // inclusive total through this half
    }
    __syncthreads();

    if (half == 1 && lane == 0) {
        float r0 = s_out[ri][0][0] + s_out[ri][1][0];
        float r1 = s_out[ri][0][1] + s_out[ri][1][1];
        float r2 = s_out[ri][0][2] + s_out[ri][1][2];
        float al = fminf(s_out[ri][1][3], 1.0f);
        out[0 * NRAYS + ray] = r0;
        out[1 * NRAYS + ray] = r1;
        out[2 * NRAYS + ray] = r2;
        out[3 * NRAYS + ray] = al;
        out[4 * NRAYS + ray] = r0;
        out[5 * NRAYS + ray] = r1;
        out[6 * NRAYS + ray] = r2;
        out[7 * NRAYS + ray] = al;
    }
}

extern "C" void kernel_launch(void* const* d_in, const int* in_sizes, int n_in,
                              void* d_out, int out_size) {
    const float* raypos    = (const float*)d_in[0];
    const float* raydir    = (const float*)d_in[1];
    const float* tminmax   = (const float*)d_in[2];
    const float* primpos   = (const float*)d_in[3];
    const float* primrot   = (const float*)d_in[4];
    const float* primscale = (const float*)d_in[5];
    const float* templ     = (const float*)d_in[6];
    float* out = (float*)d_out;

    repack_kernel<<<(NK * 4096 + 255) / 256, 256>>>(templ);
    raymarch_kernel<<<NRAYS / 2, 128>>>(raypos, raydir, tminmax,
                                        primpos, primrot, primscale, out);
}